// round 12
// baseline (speedup 1.0000x reference)
#include <cuda_runtime.h>
#include <cuda_fp16.h>

// APRConv1x1, two K=32 HMMA GEMMs + select (R5/R8/R10 proven core).
// R12 = R11 with the compile error fixed (stray placeholder call removed).
// Theory (R10 ncu: 256 of 547 L1 cyc/tile were fragment-store wavefronts):
//   outputs go to a per-warp smem obuf ([16 ch][136-word pitch], natural point
//   order), flushed by ONE lane via 16x cp.async.bulk (512B per channel row).
//   TMA engine does all global writes -> store wavefronts leave the LSU.
//   Stage shrinks to 4KB (two pack/compute phases per tile); smem 50KB/CTA
//   dynamic. Loads/pack/ldmatrix/MMA/select identical to R10.

#define THREADS 128
#define OPITCHW 136u                         // words per channel row (544 B)
#define OBUF_SZ (16u * OPITCHW * 4u)         // 8704 B per warp
#define SMEM_TOTAL (4u * 4096u + 4u * OBUF_SZ)   // 16384 + 34816 = 51200 B

__global__ __launch_bounds__(THREADS, 4)
void apr_mma8_kernel(const float* __restrict__ x,
                     const float* __restrict__ Wg,    // [16][16][4]
                     const float* __restrict__ bias,  // [16]
                     const int*   __restrict__ sidx,  // [P]
                     float* __restrict__ out,         // [B][16][N]
                     unsigned Nn, unsigned P)
{
    extern __shared__ __align__(16) char dynsmem[];

    const int tid = threadIdx.x;
    const int wid = tid >> 5;
    const int l   = tid & 31;
    const int t   = l & 3;
    const int r   = l >> 2;

    // ---- once: weight A-fragments (k = 2i + j; W_h[o][2i+j] = Wg[o*64+4i+2h+j]) ----
    unsigned a[2][2][4];
#pragma unroll
    for (int h = 0; h < 2; h++)
#pragma unroll
        for (int ks = 0; ks < 2; ks++) {
            const int i0 = 8 * ks + t;
            const int i1 = 8 * ks + 4 + t;
            float2 w; __half2 hh;
            w = *(const float2*)(Wg + r * 64 + i0 * 4 + 2 * h);
            hh = __floats2half2_rn(w.x, w.y); a[h][ks][0] = *(unsigned*)&hh;
            w = *(const float2*)(Wg + (r + 8) * 64 + i0 * 4 + 2 * h);
            hh = __floats2half2_rn(w.x, w.y); a[h][ks][1] = *(unsigned*)&hh;
            w = *(const float2*)(Wg + r * 64 + i1 * 4 + 2 * h);
            hh = __floats2half2_rn(w.x, w.y); a[h][ks][2] = *(unsigned*)&hh;
            w = *(const float2*)(Wg + (r + 8) * 64 + i1 * 4 + 2 * h);
            hh = __floats2half2_rn(w.x, w.y); a[h][ks][3] = *(unsigned*)&hh;
        }
    const float br0 = __ldg(bias + r);
    const float br8 = __ldg(bias + r + 8);

    const unsigned wtiles = (P + 127) >> 7;
    const unsigned wstep  = (unsigned)gridDim.x * 4;
    unsigned wt = (unsigned)blockIdx.x * 4 + wid;
    if (wt >= wtiles) return;

    const unsigned smem0 = (unsigned)__cvta_generic_to_shared(dynsmem);
    const unsigned sbase = smem0 + (unsigned)wid * 4096u;             // stage: 32 rows x 128B
    const unsigned obase = smem0 + 16384u + (unsigned)wid * OBUF_SZ;  // obuf

    // stage write-side (verified R8/R10 algebra): lane owns row l (pts 2l, 2l+1)
    const unsigned permw  = (((unsigned)l & 3u) << 1) | (((unsigned)l >> 2) & 1u);
    const unsigned waddr0 = sbase + ((unsigned)l << 7);
    // ldmatrix read-side
    const unsigned wrd    = ((unsigned)l & 7u) >> 1;
    const unsigned bsx    = ((((unsigned)l >> 3) << 1) + ((unsigned)l & 1u)) ^ (wrd << 1);
    const unsigned raddr0 = sbase + (wrd << 7);
    // obuf addresses for this lane (per-group offset added in loop)
    const unsigned oa_lo = obase + ((unsigned)r * OPITCHW + 2u * (unsigned)t) * 4u;
    const unsigned oa_hi = obase + (((unsigned)r + 8u) * OPITCHW + 2u * (unsigned)t) * 4u;

    // pack one 64-pt half (32 stage rows) from fv[]
    auto pack_half = [&](const float2* fv, int se, int so) {
        const unsigned she = ((unsigned)se & 1u) << 4;
        const unsigned sho = ((unsigned)so & 1u) << 4;
#pragma unroll
        for (int cc = 0; cc < 4; cc++) {
            unsigned e0, e1, e2, e3, o0, o1, o2, o3;
            e0 = (unsigned)__half_as_ushort(__float2half(fv[4*cc+0].x)) << she;
            e1 = (unsigned)__half_as_ushort(__float2half(fv[4*cc+1].x)) << she;
            e2 = (unsigned)__half_as_ushort(__float2half(fv[4*cc+2].x)) << she;
            e3 = (unsigned)__half_as_ushort(__float2half(fv[4*cc+3].x)) << she;
            o0 = (unsigned)__half_as_ushort(__float2half(fv[4*cc+0].y)) << sho;
            o1 = (unsigned)__half_as_ushort(__float2half(fv[4*cc+1].y)) << sho;
            o2 = (unsigned)__half_as_ushort(__float2half(fv[4*cc+2].y)) << sho;
            o3 = (unsigned)__half_as_ushort(__float2half(fv[4*cc+3].y)) << sho;
            const unsigned ae = waddr0 + ((((unsigned)(2*cc))     ^ permw) << 4);
            const unsigned ao = waddr0 + ((((unsigned)(2*cc + 1)) ^ permw) << 4);
            asm volatile("st.shared.v4.b32 [%0], {%1,%2,%3,%4};"
                         :: "r"(ae), "r"(e0), "r"(e1), "r"(e2), "r"(e3));
            asm volatile("st.shared.v4.b32 [%0], {%1,%2,%3,%4};"
                         :: "r"(ao), "r"(o0), "r"(o1), "r"(o2), "r"(o3));
        }
    };

    // compute 8 groups (gbias = 0 or 8): ldmatrix + 4 MMA + select -> obuf
    auto compute_half = [&](int gbias, int se, int so) {
#pragma unroll
        for (int gg = 0; gg < 8; gg++) {
            const int g = gbias + gg;
            const unsigned addr = raddr0 + ((unsigned)gg << 9)
                                + ((bsx ^ ((unsigned)gg & 1u)) << 4);
            unsigned b0, b1, b2, b3;
            asm volatile("ldmatrix.sync.aligned.m8n8.x4.shared.b16 {%0,%1,%2,%3}, [%4];"
                         : "=r"(b0), "=r"(b1), "=r"(b2), "=r"(b3) : "r"(addr));

            float dl0 = br0, dl1 = br0, dl2 = br8, dl3 = br8;
            float dh0 = br0, dh1 = br0, dh2 = br8, dh3 = br8;

            asm volatile("mma.sync.aligned.m16n8k16.row.col.f32.f16.f16.f32 "
                "{%0,%1,%2,%3}, {%4,%5,%6,%7}, {%8,%9}, {%0,%1,%2,%3};"
                : "+f"(dl0), "+f"(dl1), "+f"(dl2), "+f"(dl3)
                : "r"(a[0][0][0]), "r"(a[0][0][1]), "r"(a[0][0][2]), "r"(a[0][0][3]),
                  "r"(b0), "r"(b1));
            asm volatile("mma.sync.aligned.m16n8k16.row.col.f32.f16.f16.f32 "
                "{%0,%1,%2,%3}, {%4,%5,%6,%7}, {%8,%9}, {%0,%1,%2,%3};"
                : "+f"(dl0), "+f"(dl1), "+f"(dl2), "+f"(dl3)
                : "r"(a[0][1][0]), "r"(a[0][1][1]), "r"(a[0][1][2]), "r"(a[0][1][3]),
                  "r"(b2), "r"(b3));
            asm volatile("mma.sync.aligned.m16n8k16.row.col.f32.f16.f16.f32 "
                "{%0,%1,%2,%3}, {%4,%5,%6,%7}, {%8,%9}, {%0,%1,%2,%3};"
                : "+f"(dh0), "+f"(dh1), "+f"(dh2), "+f"(dh3)
                : "r"(a[1][0][0]), "r"(a[1][0][1]), "r"(a[1][0][2]), "r"(a[1][0][3]),
                  "r"(b0), "r"(b1));
            asm volatile("mma.sync.aligned.m16n8k16.row.col.f32.f16.f16.f32 "
                "{%0,%1,%2,%3}, {%4,%5,%6,%7}, {%8,%9}, {%0,%1,%2,%3};"
                : "+f"(dh0), "+f"(dh1), "+f"(dh2), "+f"(dh3)
                : "r"(a[1][1][0]), "r"(a[1][1][1]), "r"(a[1][1][2]), "r"(a[1][1][3]),
                  "r"(b2), "r"(b3));

            const int src = 4 * gg + t;
            const int ss0 = __shfl_sync(0xffffffffu, se, src);
            const int ss1 = __shfl_sync(0xffffffffu, so, src);
            const float q0 = (ss0 & 2) ? dh0 : dl0;
            const float q1 = (ss1 & 2) ? dh1 : dl1;
            const float q2 = (ss0 & 2) ? dh2 : dl2;
            const float q3 = (ss1 & 2) ? dh3 : dl3;

            const unsigned po = (unsigned)(8 * g) * 4u;   // point byte offset
            asm volatile("st.shared.v2.f32 [%0], {%1,%2};"
                         :: "r"(oa_lo + po), "f"(q0), "f"(q1));
            asm volatile("st.shared.v2.f32 [%0], {%1,%2};"
                         :: "r"(oa_hi + po), "f"(q2), "f"(q3));
        }
    };

    // ---- prologue: load tile wt ----
    float2 fv0[16], fv1[16]; int2 sv0, sv1;
    {
        unsigned wtb = wt << 7; if (wtb + 128u > P) wtb = P - 128u;
        const unsigned b  = wtb >= Nn ? 1u : 0u;
        const unsigned n0 = wtb - b * Nn;
        const float* xp = x + (size_t)b * 16u * Nn + n0 + 2u * (unsigned)l;
#pragma unroll
        for (int i = 0; i < 16; i++) {
            fv0[i] = *reinterpret_cast<const float2*>(xp + (size_t)((unsigned)i * Nn));
            fv1[i] = *reinterpret_cast<const float2*>(xp + (size_t)((unsigned)i * Nn) + 64u);
        }
        sv0 = *reinterpret_cast<const int2*>(sidx + wtb + 2u * (unsigned)l);
        sv1 = *reinterpret_cast<const int2*>(sidx + wtb + 64u + 2u * (unsigned)l);
    }

    for (;;) {
        unsigned wtb = wt << 7; if (wtb + 128u > P) wtb = P - 128u;
        const unsigned b  = wtb >= Nn ? 1u : 0u;
        const unsigned n0 = wtb - b * Nn;
        float* fo = out + (size_t)b * 16u * Nn + n0;

        const int se0 = sv0.x, so0 = sv0.y, se1 = sv1.x, so1 = sv1.y;

        const unsigned wtn = wt + wstep;
        const bool more = wtn < wtiles;
        unsigned wtb2 = wtn << 7; if (wtb2 + 128u > P) wtb2 = P - 128u;
        const unsigned b2 = wtb2 >= Nn ? 1u : 0u;
        const float* xp2 = x + (size_t)b2 * 16u * Nn + (wtb2 - b2 * Nn) + 2u * (unsigned)l;

        // ---- phase A: pack half 0, prefetch half 0 of next tile ----
        pack_half(fv0, se0, so0);
        if (more) {
#pragma unroll
            for (int i = 0; i < 16; i++)
                fv0[i] = *reinterpret_cast<const float2*>(xp2 + (size_t)((unsigned)i * Nn));
            sv0 = *reinterpret_cast<const int2*>(sidx + wtb2 + 2u * (unsigned)l);
        }
        if (l == 0)  // prior flush must finish reading obuf before we refill it
            asm volatile("cp.async.bulk.wait_group.read 0;" ::: "memory");
        __syncwarp();
        compute_half(0, se0, so0);
        __syncwarp();

        // ---- phase B: pack half 1, prefetch half 1 of next tile ----
        pack_half(fv1, se1, so1);
        if (more) {
#pragma unroll
            for (int i = 0; i < 16; i++)
                fv1[i] = *reinterpret_cast<const float2*>(xp2 + (size_t)((unsigned)i * Nn) + 64u);
            sv1 = *reinterpret_cast<const int2*>(sidx + wtb2 + 64u + 2u * (unsigned)l);
        }
        __syncwarp();
        compute_half(8, se1, so1);
        __syncwarp();

        // ---- flush: 16 channel rows via TMA bulk copy ----
        if (l == 0) {
            asm volatile("fence.proxy.async.shared::cta;" ::: "memory");
#pragma unroll
            for (int c = 0; c < 16; c++) {
                const unsigned long long dst =
                    (unsigned long long)(fo + (size_t)((unsigned)c * Nn));
                const unsigned src = obase + (unsigned)c * (OPITCHW * 4u);
                asm volatile("cp.async.bulk.global.shared::cta.bulk_group [%0], [%1], %2;"
                             :: "l"(dst), "r"(src), "r"(512u) : "memory");
            }
            asm volatile("cp.async.bulk.commit_group;" ::: "memory");
        }

        if (!more) break;
        wt = wtn;
    }

    // drain outstanding bulk stores before exit
    if (l == 0)
        asm volatile("cp.async.bulk.wait_group 0;" ::: "memory");
}

extern "C" void kernel_launch(void* const* d_in, const int* in_sizes, int n_in,
                              void* d_out, int out_size)
{
    const float* x    = (const float*)d_in[0];   // [B, 16, N]
    const float* Wg   = (const float*)d_in[1];   // [16, 16, 4, 1, 1]
    const float* bias = (const float*)d_in[2];   // [16]
    const int*   sidx = (const int*)d_in[3];     // [B, N]

    float* out = (float*)d_out;

    const unsigned P  = (unsigned)in_sizes[3];   // B*N
    const unsigned Nn = P / 2;                   // B = 2

    static int attr_set = 0;
    if (!attr_set) {
        cudaFuncSetAttribute(apr_mma8_kernel,
                             cudaFuncAttributeMaxDynamicSharedMemorySize,
                             (int)SMEM_TOTAL);
        attr_set = 1;
    }

    const unsigned wtiles = (P + 127) / 128;
    unsigned blk = (wtiles + 3) / 4;
    if (blk > 592) blk = 592;                    // 4 CTAs x 148 SMs, persistent

    apr_mma8_kernel<<<blk, THREADS, SMEM_TOTAL>>>(x, Wg, bias, sidx, out, Nn, P);
}

// round 13
// speedup vs baseline: 1.1553x; 1.1553x over previous
#include <cuda_runtime.h>
#include <cuda_fp16.h>

// APRConv1x1, two K=32 HMMA GEMMs + select (R5/R8/R10 proven core).
// R13 = R10 champion + serial-chain compression:
//  - replace 32 shfl/tile (26-cyc MIO ops gating select->store) with
//    4 ballot_sync/tile + per-group bit extract (pure ALU, no MIO)
//  - __ldg on x/sidx loads (non-coherent, no L1 allocate)
// Engine otherwise byte-identical to R10 (94.4us, DRAM 72.1%).

#define THREADS 128

__global__ __launch_bounds__(THREADS, 4)
void apr_mma9_kernel(const float* __restrict__ x,
                     const float* __restrict__ Wg,    // [16][16][4]
                     const float* __restrict__ bias,  // [16]
                     const int*   __restrict__ sidx,  // [P]
                     float* __restrict__ out,         // [B][16][N]
                     unsigned Nn, unsigned P)
{
    __shared__ __align__(16) char stage[4][8192];   // 64 rows x 128B per warp

    const int tid = threadIdx.x;
    const int wid = tid >> 5;
    const int l   = tid & 31;
    const int t   = l & 3;
    const int r   = l >> 2;

    // ---- once: weight A-fragments (k = 2i + j; W_h[o][2i+j] = Wg[o*64+4i+2h+j]) ----
    unsigned a[2][2][4];
#pragma unroll
    for (int h = 0; h < 2; h++)
#pragma unroll
        for (int ks = 0; ks < 2; ks++) {
            const int i0 = 8 * ks + t;
            const int i1 = 8 * ks + 4 + t;
            float2 w; __half2 hh;
            w = *(const float2*)(Wg + r * 64 + i0 * 4 + 2 * h);
            hh = __floats2half2_rn(w.x, w.y); a[h][ks][0] = *(unsigned*)&hh;
            w = *(const float2*)(Wg + (r + 8) * 64 + i0 * 4 + 2 * h);
            hh = __floats2half2_rn(w.x, w.y); a[h][ks][1] = *(unsigned*)&hh;
            w = *(const float2*)(Wg + r * 64 + i1 * 4 + 2 * h);
            hh = __floats2half2_rn(w.x, w.y); a[h][ks][2] = *(unsigned*)&hh;
            w = *(const float2*)(Wg + (r + 8) * 64 + i1 * 4 + 2 * h);
            hh = __floats2half2_rn(w.x, w.y); a[h][ks][3] = *(unsigned*)&hh;
        }
    const float br0 = __ldg(bias + r);
    const float br8 = __ldg(bias + r + 8);

    const unsigned wtiles = (P + 127) >> 7;
    const unsigned wstep  = (unsigned)gridDim.x * 4;
    unsigned wt = (unsigned)blockIdx.x * 4 + wid;
    if (wt >= wtiles) return;

    const unsigned sbase = (unsigned)__cvta_generic_to_shared(stage[wid]);

    // write-side: lane owns rows l (pts 2l,2l+1) and l+32 (pts 64+2l,64+2l+1)
    const unsigned permw  = (((unsigned)l & 3u) << 1) | (((unsigned)l >> 2) & 1u);
    const unsigned waddr0 = sbase + ((unsigned)l << 7);       // +4096 for row l+32
    // read-side (ldmatrix), verified slot algebra
    const unsigned wrd    = ((unsigned)l & 7u) >> 1;
    const unsigned bsx    = ((((unsigned)l >> 3) << 1) + ((unsigned)l & 1u)) ^ (wrd << 1);
    const unsigned raddr0 = sbase + (wrd << 7);
    // store row offsets
    const unsigned ro  = (unsigned)r * Nn;
    const unsigned ro8 = (unsigned)(r + 8) * Nn;

    // ---- prologue: load tile wt ----
    float2 fv0[16], fv1[16]; int2 sv0, sv1;
    {
        unsigned wtb = wt << 7; if (wtb + 128u > P) wtb = P - 128u;
        const unsigned b  = wtb >= Nn ? 1u : 0u;
        const unsigned n0 = wtb - b * Nn;
        const float* xp = x + (size_t)b * 16u * Nn + n0 + 2u * (unsigned)l;
#pragma unroll
        for (int i = 0; i < 16; i++) {
            fv0[i] = __ldg(reinterpret_cast<const float2*>(xp + (size_t)((unsigned)i * Nn)));
            fv1[i] = __ldg(reinterpret_cast<const float2*>(xp + (size_t)((unsigned)i * Nn) + 64u));
        }
        sv0 = __ldg(reinterpret_cast<const int2*>(sidx + wtb + 2u * (unsigned)l));
        sv1 = __ldg(reinterpret_cast<const int2*>(sidx + wtb + 64u + 2u * (unsigned)l));
    }

    for (;;) {
        unsigned wtb = wt << 7; if (wtb + 128u > P) wtb = P - 128u;
        const unsigned b  = wtb >= Nn ? 1u : 0u;
        const unsigned n0 = wtb - b * Nn;
        float* fo = out + (size_t)b * 16u * Nn + n0;

        // keep current tile's stencil bits + warp-wide select masks (ballot)
        const int se0 = sv0.x, so0 = sv0.y, se1 = sv1.x, so1 = sv1.y;
        const unsigned be0 = __ballot_sync(0xffffffffu, (se0 >> 1) & 1);
        const unsigned bo0 = __ballot_sync(0xffffffffu, (so0 >> 1) & 1);
        const unsigned be1 = __ballot_sync(0xffffffffu, (se1 >> 1) & 1);
        const unsigned bo1 = __ballot_sync(0xffffffffu, (so1 >> 1) & 1);

        // ---- pack + stage both halves (16x STS.128, conflict-free) ----
        {
            const unsigned she = ((unsigned)se0 & 1u) << 4;
            const unsigned sho = ((unsigned)so0 & 1u) << 4;
#pragma unroll
            for (int cc = 0; cc < 4; cc++) {
                unsigned e0, e1, e2, e3, o0, o1, o2, o3;
                e0 = (unsigned)__half_as_ushort(__float2half(fv0[4*cc+0].x)) << she;
                e1 = (unsigned)__half_as_ushort(__float2half(fv0[4*cc+1].x)) << she;
                e2 = (unsigned)__half_as_ushort(__float2half(fv0[4*cc+2].x)) << she;
                e3 = (unsigned)__half_as_ushort(__float2half(fv0[4*cc+3].x)) << she;
                o0 = (unsigned)__half_as_ushort(__float2half(fv0[4*cc+0].y)) << sho;
                o1 = (unsigned)__half_as_ushort(__float2half(fv0[4*cc+1].y)) << sho;
                o2 = (unsigned)__half_as_ushort(__float2half(fv0[4*cc+2].y)) << sho;
                o3 = (unsigned)__half_as_ushort(__float2half(fv0[4*cc+3].y)) << sho;
                const unsigned ae = waddr0 + ((((unsigned)(2*cc))     ^ permw) << 4);
                const unsigned ao = waddr0 + ((((unsigned)(2*cc + 1)) ^ permw) << 4);
                asm volatile("st.shared.v4.b32 [%0], {%1,%2,%3,%4};"
                             :: "r"(ae), "r"(e0), "r"(e1), "r"(e2), "r"(e3));
                asm volatile("st.shared.v4.b32 [%0], {%1,%2,%3,%4};"
                             :: "r"(ao), "r"(o0), "r"(o1), "r"(o2), "r"(o3));
            }
        }
        {
            const unsigned she = ((unsigned)se1 & 1u) << 4;
            const unsigned sho = ((unsigned)so1 & 1u) << 4;
#pragma unroll
            for (int cc = 0; cc < 4; cc++) {
                unsigned e0, e1, e2, e3, o0, o1, o2, o3;
                e0 = (unsigned)__half_as_ushort(__float2half(fv1[4*cc+0].x)) << she;
                e1 = (unsigned)__half_as_ushort(__float2half(fv1[4*cc+1].x)) << she;
                e2 = (unsigned)__half_as_ushort(__float2half(fv1[4*cc+2].x)) << she;
                e3 = (unsigned)__half_as_ushort(__float2half(fv1[4*cc+3].x)) << she;
                o0 = (unsigned)__half_as_ushort(__float2half(fv1[4*cc+0].y)) << sho;
                o1 = (unsigned)__half_as_ushort(__float2half(fv1[4*cc+1].y)) << sho;
                o2 = (unsigned)__half_as_ushort(__float2half(fv1[4*cc+2].y)) << sho;
                o3 = (unsigned)__half_as_ushort(__float2half(fv1[4*cc+3].y)) << sho;
                const unsigned ae = waddr0 + 4096u + ((((unsigned)(2*cc))     ^ permw) << 4);
                const unsigned ao = waddr0 + 4096u + ((((unsigned)(2*cc + 1)) ^ permw) << 4);
                asm volatile("st.shared.v4.b32 [%0], {%1,%2,%3,%4};"
                             :: "r"(ae), "r"(e0), "r"(e1), "r"(e2), "r"(e3));
                asm volatile("st.shared.v4.b32 [%0], {%1,%2,%3,%4};"
                             :: "r"(ao), "r"(o0), "r"(o1), "r"(o2), "r"(o3));
            }
        }

        // ---- prefetch next tile into the SAME registers (WAR after pack) ----
        const unsigned wtn = wt + wstep;
        const bool more = wtn < wtiles;
        if (more) {
            unsigned wtb2 = wtn << 7; if (wtb2 + 128u > P) wtb2 = P - 128u;
            const unsigned b2 = wtb2 >= Nn ? 1u : 0u;
            const unsigned n2 = wtb2 - b2 * Nn;
            const float* xp = x + (size_t)b2 * 16u * Nn + n2 + 2u * (unsigned)l;
#pragma unroll
            for (int i = 0; i < 16; i++) {
                fv0[i] = __ldg(reinterpret_cast<const float2*>(xp + (size_t)((unsigned)i * Nn)));
                fv1[i] = __ldg(reinterpret_cast<const float2*>(xp + (size_t)((unsigned)i * Nn) + 64u));
            }
            sv0 = __ldg(reinterpret_cast<const int2*>(sidx + wtb2 + 2u * (unsigned)l));
            sv1 = __ldg(reinterpret_cast<const int2*>(sidx + wtb2 + 64u + 2u * (unsigned)l));
        }
        __syncwarp();

        // ---- compute: 16 groups of 8 points ----
#pragma unroll
        for (int g = 0; g < 16; g++) {
            const unsigned addr = raddr0 + ((unsigned)g << 9)
                                + ((bsx ^ ((unsigned)g & 1u)) << 4);
            unsigned b0, b1, b2, b3;
            asm volatile("ldmatrix.sync.aligned.m8n8.x4.shared.b16 {%0,%1,%2,%3}, [%4];"
                         : "=r"(b0), "=r"(b1), "=r"(b2), "=r"(b3) : "r"(addr));

            float dl0 = br0, dl1 = br0, dl2 = br8, dl3 = br8;
            float dh0 = br0, dh1 = br0, dh2 = br8, dh3 = br8;

            asm volatile("mma.sync.aligned.m16n8k16.row.col.f32.f16.f16.f32 "
                "{%0,%1,%2,%3}, {%4,%5,%6,%7}, {%8,%9}, {%0,%1,%2,%3};"
                : "+f"(dl0), "+f"(dl1), "+f"(dl2), "+f"(dl3)
                : "r"(a[0][0][0]), "r"(a[0][0][1]), "r"(a[0][0][2]), "r"(a[0][0][3]),
                  "r"(b0), "r"(b1));
            asm volatile("mma.sync.aligned.m16n8k16.row.col.f32.f16.f16.f32 "
                "{%0,%1,%2,%3}, {%4,%5,%6,%7}, {%8,%9}, {%0,%1,%2,%3};"
                : "+f"(dl0), "+f"(dl1), "+f"(dl2), "+f"(dl3)
                : "r"(a[0][1][0]), "r"(a[0][1][1]), "r"(a[0][1][2]), "r"(a[0][1][3]),
                  "r"(b2), "r"(b3));
            asm volatile("mma.sync.aligned.m16n8k16.row.col.f32.f16.f16.f32 "
                "{%0,%1,%2,%3}, {%4,%5,%6,%7}, {%8,%9}, {%0,%1,%2,%3};"
                : "+f"(dh0), "+f"(dh1), "+f"(dh2), "+f"(dh3)
                : "r"(a[1][0][0]), "r"(a[1][0][1]), "r"(a[1][0][2]), "r"(a[1][0][3]),
                  "r"(b0), "r"(b1));
            asm volatile("mma.sync.aligned.m16n8k16.row.col.f32.f16.f16.f32 "
                "{%0,%1,%2,%3}, {%4,%5,%6,%7}, {%8,%9}, {%0,%1,%2,%3};"
                : "+f"(dh0), "+f"(dh1), "+f"(dh2), "+f"(dh3)
                : "r"(a[1][1][0]), "r"(a[1][1][1]), "r"(a[1][1][2]), "r"(a[1][1][3]),
                  "r"(b2), "r"(b3));

            // select via ballot masks (no shfl): owner lane bit = 4g+t (half 0)
            // or 4(g-8)+t (half 1)
            unsigned ss0, ss1;
            if (g < 8) {
                const int src = 4 * g + t;
                ss0 = (be0 >> src) & 1u;
                ss1 = (bo0 >> src) & 1u;
            } else {
                const int src = 4 * (g - 8) + t;
                ss0 = (be1 >> src) & 1u;
                ss1 = (bo1 >> src) & 1u;
            }
            const float q0 = ss0 ? dh0 : dl0;
            const float q1 = ss1 ? dh1 : dl1;
            const float q2 = ss0 ? dh2 : dl2;
            const float q3 = ss1 ? dh3 : dl3;

            const unsigned p0 = (unsigned)(8 * g + 2 * t);
            *reinterpret_cast<float2*>(fo + ro  + p0) = make_float2(q0, q1);
            *reinterpret_cast<float2*>(fo + ro8 + p0) = make_float2(q2, q3);
        }
        __syncwarp();   // ldmatrix reads done before next iteration's STS

        if (!more) break;
        wt = wtn;
    }
}

extern "C" void kernel_launch(void* const* d_in, const int* in_sizes, int n_in,
                              void* d_out, int out_size)
{
    const float* x    = (const float*)d_in[0];   // [B, 16, N]
    const float* Wg   = (const float*)d_in[1];   // [16, 16, 4, 1, 1]
    const float* bias = (const float*)d_in[2];   // [16]
    const int*   sidx = (const int*)d_in[3];     // [B, N]

    float* out = (float*)d_out;

    const unsigned P  = (unsigned)in_sizes[3];   // B*N
    const unsigned Nn = P / 2;                   // B = 2

    const unsigned wtiles = (P + 127) / 128;
    unsigned blk = (wtiles + 3) / 4;
    if (blk > 592) blk = 592;                    // 4 CTAs x 148 SMs, persistent

    apr_mma9_kernel<<<blk, THREADS>>>(x, Wg, bias, sidx, out, Nn, P);
}